// round 6
// baseline (speedup 1.0000x reference)
#include <cuda_runtime.h>

// DiffAugment, two-kernel version.
// B=128, C=3, H=W=256 fp32. shift=32, cut=51 (half=25).
// Identity: global mean after brightness+saturation == mean(x_raw) + (r_bright-0.5).
//
// R4: aug stages source rows into smem via aligned float4 loads (kills the
//     misaligned 2-sector scalar LDGs), computes with conflict-free strided
//     LDS; sum limits front-batched MLP to 4 to avoid L1tex-queue spread.

#define EPB 196608   // 3*256*256

__device__ float g_part[1024];   // 8 partials per batch

__global__ void __launch_bounds__(256) sum_kernel(const float* __restrict__ x) {
    int blk = blockIdx.x;           // 0..1023 : batch = blk>>3
    int t = threadIdx.x;
    const float4* p = reinterpret_cast<const float4*>(x) + (size_t)blk * 6144 + t;
    float s = 0.f;
#pragma unroll 1
    for (int k0 = 0; k0 < 24; k0 += 4) {
        float4 a = p[(k0 + 0) * 256];
        float4 b = p[(k0 + 1) * 256];
        float4 c = p[(k0 + 2) * 256];
        float4 d = p[(k0 + 3) * 256];
        s += ((a.x + a.y) + (a.z + a.w)) + ((b.x + b.y) + (b.z + b.w))
           + ((c.x + c.y) + (c.z + c.w)) + ((d.x + d.y) + (d.z + d.w));
    }
#pragma unroll
    for (int o = 16; o; o >>= 1) s += __shfl_down_sync(0xffffffffu, s, o);
    __shared__ float sh[8];
    if ((t & 31) == 0) sh[t >> 5] = s;
    __syncthreads();
    if (t == 0) {
        g_part[blk] = sh[0] + sh[1] + sh[2] + sh[3] + sh[4] + sh[5] + sh[6] + sh[7];
    }
}

// Each block: one batch b, 4 output rows h0..h0+3, all 3 channels.
// Stage: 12 source rows (3 ch x 4 rows) as aligned float4 -> smem (12 KB).
// Compute: thread (r = t>>6, c = t&63) handles cols {c, c+64, c+128, c+192}.
__global__ void __launch_bounds__(256) aug_kernel(
    const float* __restrict__ x,
    const float* __restrict__ rb, const float* __restrict__ rs, const float* __restrict__ rc,
    const int* __restrict__ txv, const int* __restrict__ tyv,
    const int* __restrict__ oxv, const int* __restrict__ oyv,
    float* __restrict__ out)
{
    __shared__ float sm[12 * 256];          // [ch*4 + r][col]

    const int blk = blockIdx.x;             // 0..8191
    const int t   = threadIdx.x;
    const int b   = blk >> 6;
    const int h0  = (blk & 63) << 2;

    const int tx = __ldg(txv + b) - 32;
    const int ty = __ldg(tyv + b) - 32;
    const int ox = __ldg(oxv + b);
    const int oy = __ldg(oyv + b);

    const float rbm = __ldg(rb + b) - 0.5f;
    const float s2  = __ldg(rs + b) * 2.0f;
    const float cc  = __ldg(rc + b) + 0.5f;
    const float4* gp = reinterpret_cast<const float4*>(g_part) + 2 * b;
    float4 p0 = gp[0], p1 = gp[1];
    const float g = (((p0.x + p0.y) + (p0.z + p0.w)) + ((p1.x + p1.y) + (p1.z + p1.w)))
                    * (1.0f / 196608.0f) + rbm;

    // ---- stage 12 rows, aligned float4, zero-fill OOB rows ----
    {
        const float4* xb4 = reinterpret_cast<const float4*>(x) + (size_t)b * 49152;
        float4* smv = reinterpret_cast<float4*>(sm);
#pragma unroll
        for (int i = 0; i < 3; ++i) {
            int e    = t + i * 256;          // 0..767
            int rcix = e >> 6;               // 0..11 = ch*4 + r
            int col4 = e & 63;
            int ch   = rcix >> 2;
            int r    = rcix & 3;
            int sr   = h0 + r + tx;
            float4 v = make_float4(0.f, 0.f, 0.f, 0.f);
            if ((unsigned)sr < 256u)
                v = xb4[ch * 16384 + sr * 64 + col4];
            smv[rcix * 64 + col4] = v;
        }
    }
    __syncthreads();

    // ---- compute + store ----
    const int r = t >> 6;                    // 0..3
    const int c = t & 63;
    const int h = h0 + r;
    const bool row_ok  = ((unsigned)(h + tx)) < 256u;
    const bool cut_row = (h >= ox - 25) && (h <= ox + 25);

    const float* s0 = sm + (0 * 4 + r) * 256;
    const float* s1 = sm + (1 * 4 + r) * 256;
    const float* s2r = sm + (2 * 4 + r) * 256;
    float* ob = out + (size_t)b * EPB + h * 256;

#pragma unroll
    for (int j = 0; j < 4; ++j) {
        int w  = c + (j << 6);
        int sw = w + ty;
        bool inb = (unsigned)sw < 256u;
        float v0 = inb ? s0[sw]  : 0.f;
        float v1 = inb ? s1[sw]  : 0.f;
        float v2 = inb ? s2r[sw] : 0.f;
        bool ok = row_ok && inb &&
                  !(cut_row && (w >= oy - 25) && (w <= oy + 25));
        float m  = (v0 + v1 + v2) * (1.0f / 3.0f);
        float mb = m + rbm;
        float a0 = fmaf(fmaf(v0 - m, s2, mb) - g, cc, g);
        float a1 = fmaf(fmaf(v1 - m, s2, mb) - g, cc, g);
        float a2 = fmaf(fmaf(v2 - m, s2, mb) - g, cc, g);
        __stcs(ob + w,           ok ? a0 : 0.f);
        __stcs(ob + w + 65536,   ok ? a1 : 0.f);
        __stcs(ob + w + 131072,  ok ? a2 : 0.f);
    }
}

extern "C" void kernel_launch(void* const* d_in, const int* in_sizes, int n_in,
                              void* d_out, int out_size) {
    const float* x  = (const float*)d_in[0];
    const float* rb = (const float*)d_in[1];
    const float* rs = (const float*)d_in[2];
    const float* rc = (const float*)d_in[3];
    const int*   tx = (const int*)d_in[4];
    const int*   ty = (const int*)d_in[5];
    const int*   ox = (const int*)d_in[6];
    const int*   oy = (const int*)d_in[7];
    float* out = (float*)d_out;

    sum_kernel<<<1024, 256>>>(x);
    aug_kernel<<<8192, 256>>>(x, rb, rs, rc, tx, ty, ox, oy, out);
}